// round 10
// baseline (speedup 1.0000x reference)
#include <cuda_runtime.h>
#include <cuda_bf16.h>

#define NBATCH 32
#define NSUP   100
#define NWAY   10
#define NZV    1000
#define NQRY   150

// ---------------- device scratch ----------------
__device__ float g_krn   [NBATCH * NSUP * NSUP];          // sup sup^T (bitwise symmetric)
__device__ float g_compat[NBATCH * NSUP * NQRY];
__device__ float g_Hinv  [NBATCH * NWAY * NSUP * NSUP];   // row-major per (b,c); symmetric
__device__ float g_t     [NBATCH * NWAY * NSUP];
// all NZV-state arrays use i2 = c*100 + ss layout
__device__ float g_z  [NBATCH * NZV];
__device__ float g_s  [NBATCH * NZV];
__device__ float g_lam[NBATCH * NZV];
__device__ float g_gz [NBATCH * NZV];
__device__ float g_rp [NBATCH * NZV];
__device__ float g_rc [NBATCH * NZV];
__device__ float g_r1 [NBATCH * NZV];
__device__ float g_d  [NBATCH * NZV];
__device__ float g_nu [NBATCH * NSUP];
__device__ float g_rp2[NBATCH * NSUP];

// ---------------- gram: kernel (100x100) + compat (100x150) ----------------
__global__ void __launch_bounds__(400) k_gram(const float* __restrict__ sup,
                                              const float* __restrict__ qry) {
    int b  = blockIdx.x;
    int c0 = blockIdx.y * 64;
    __shared__ __align__(16) float As[32 * 100];
    __shared__ __align__(16) float Bs[32 * 64];
    int tid = threadIdx.x;
    int tx = tid & 15;
    int ty = tid >> 4;
    float acc[4][4];
#pragma unroll
    for (int u = 0; u < 4; u++)
#pragma unroll
        for (int v = 0; v < 4; v++) acc[u][v] = 0.f;

    const float* supb = sup + (size_t)b * NSUP * 512;
    const float* qryb = qry + (size_t)b * NQRY * 512;

    for (int kt = 0; kt < 512; kt += 32) {
        __syncthreads();
        for (int e = tid; e < NSUP * 32; e += 400) {
            int r = e >> 5, kk = e & 31;
            As[kk * 100 + r] = supb[r * 512 + kt + kk];
        }
        for (int e = tid; e < 64 * 32; e += 400) {
            int cc = e >> 5, kk = e & 31;
            int col = c0 + cc;
            float v = 0.f;
            if (col < NSUP)      v = supb[col * 512 + kt + kk];
            else if (col < 250)  v = qryb[(col - NSUP) * 512 + kt + kk];
            Bs[kk * 64 + cc] = v;
        }
        __syncthreads();
#pragma unroll
        for (int kk = 0; kk < 32; kk++) {
            float4 a  = *(const float4*)(As + kk * 100 + 4 * ty);
            float4 bb = *(const float4*)(Bs + kk * 64 + 4 * tx);
            acc[0][0] = fmaf(a.x, bb.x, acc[0][0]); acc[0][1] = fmaf(a.x, bb.y, acc[0][1]);
            acc[0][2] = fmaf(a.x, bb.z, acc[0][2]); acc[0][3] = fmaf(a.x, bb.w, acc[0][3]);
            acc[1][0] = fmaf(a.y, bb.x, acc[1][0]); acc[1][1] = fmaf(a.y, bb.y, acc[1][1]);
            acc[1][2] = fmaf(a.y, bb.z, acc[1][2]); acc[1][3] = fmaf(a.y, bb.w, acc[1][3]);
            acc[2][0] = fmaf(a.z, bb.x, acc[2][0]); acc[2][1] = fmaf(a.z, bb.y, acc[2][1]);
            acc[2][2] = fmaf(a.z, bb.z, acc[2][2]); acc[2][3] = fmaf(a.z, bb.w, acc[2][3]);
            acc[3][0] = fmaf(a.w, bb.x, acc[3][0]); acc[3][1] = fmaf(a.w, bb.y, acc[3][1]);
            acc[3][2] = fmaf(a.w, bb.z, acc[3][2]); acc[3][3] = fmaf(a.w, bb.w, acc[3][3]);
        }
    }
#pragma unroll
    for (int u = 0; u < 4; u++) {
        int r = 4 * ty + u;
#pragma unroll
        for (int v = 0; v < 4; v++) {
            int col = c0 + 4 * tx + v;
            if (col < NSUP)
                g_krn[b * NSUP * NSUP + r * NSUP + col] = acc[u][v];
            else if (col < 250)
                g_compat[b * NSUP * NQRY + r * NQRY + (col - NSUP)] = acc[u][v];
        }
    }
}

// ---------------- init (i2 layout) ----------------
__global__ void __launch_bounds__(256) k_init(const int* __restrict__ lab) {
    int b = blockIdx.x, tid = threadIdx.x;
    for (int i = tid; i < NZV; i += 256) {
        int gi = b * NZV + i;
        int ss = i % NSUP, c = i / NSUP;
        float y = (lab[b * NSUP + ss] == c) ? 1.f : 0.f;
        g_z[gi] = 0.f; g_s[gi] = 1.f; g_lam[gi] = 1.f; g_gz[gi] = 0.f;
        float rd = 1.f - y;
        float rp = 1.f - 0.1f * y;
        float rc = 0.9f;
        g_rp[gi] = rp;
        g_rc[gi] = rc;
        g_d [gi] = 1.f;
        g_r1[gi] = -rd + (rc - rp);
    }
    for (int ss = tid; ss < NSUP; ss += 256) {
        g_nu [b * NSUP + ss] = 0.f;
        g_rp2[b * NSUP + ss] = 0.f;
    }
}

// ---------------- 4-matrix symmetric sweep (rotated row ownership) ----------------
// Thread owns row rmv[m] of matrix m, columns [base, base+28) of the 112-wide
// augmented row (col 100 = rhs border). srow = per-matrix double-buffered pivot row.
__device__ __forceinline__ void sweep4(float A[4][28],
                                       float srow[4][2][112],
                                       const int* rmv, int base) {
    for (int k = 0; k < NSUP; k++) {
        int buf = k & 1, nb = buf ^ 1;
#pragma unroll
        for (int m = 0; m < 4; m++) {
            const float* row = srow[m][buf];
            int rm = rmv[m];
            float invp = __fdividef(1.0f, row[k]);
            float sr = row[rm];
            const float4* rowv = (const float4*)(row + base);
            float* Am = A[m];
            if (rm == k) {
#pragma unroll
                for (int mm = 0; mm < 7; mm++) {
                    float4 p = rowv[mm];
                    int j = base + 4 * mm;
                    Am[4*mm+0] = (j+0 == k) ? invp : p.x * invp;
                    Am[4*mm+1] = (j+1 == k) ? invp : p.y * invp;
                    Am[4*mm+2] = (j+2 == k) ? invp : p.z * invp;
                    Am[4*mm+3] = (j+3 == k) ? invp : p.w * invp;
                }
            } else {
                float t = (rm < k) ? -sr * invp : sr * invp;
                if (k >= base && k < base + 28) {
#pragma unroll
                    for (int mm = 0; mm < 7; mm++) {
                        float4 p = rowv[mm];
                        int j = base + 4 * mm;
                        float u0 = fmaf(-t, p.x, Am[4*mm+0]);
                        float u1 = fmaf(-t, p.y, Am[4*mm+1]);
                        float u2 = fmaf(-t, p.z, Am[4*mm+2]);
                        float u3 = fmaf(-t, p.w, Am[4*mm+3]);
                        Am[4*mm+0] = (j+0 == k) ? -t : u0;
                        Am[4*mm+1] = (j+1 == k) ? -t : u1;
                        Am[4*mm+2] = (j+2 == k) ? -t : u2;
                        Am[4*mm+3] = (j+3 == k) ? -t : u3;
                    }
                } else {
#pragma unroll
                    for (int mm = 0; mm < 7; mm++) {
                        float4 p = rowv[mm];
                        Am[4*mm+0] = fmaf(-t, p.x, Am[4*mm+0]);
                        Am[4*mm+1] = fmaf(-t, p.y, Am[4*mm+1]);
                        Am[4*mm+2] = fmaf(-t, p.z, Am[4*mm+2]);
                        Am[4*mm+3] = fmaf(-t, p.w, Am[4*mm+3]);
                    }
                }
            }
            if (rm == k + 1) {
                float4* dst = (float4*)(srow[m][nb] + base);
#pragma unroll
                for (int mm = 0; mm < 7; mm++)
                    dst[mm] = make_float4(Am[4*mm], Am[4*mm+1], Am[4*mm+2], Am[4*mm+3]);
            }
        }
        __syncthreads();
    }
}

// ---------------- per-class inversion: 4 matrices/block (grid=80, block=400) ----------------
__global__ void __launch_bounds__(400, 1) k_invert4() {
    int tid = threadIdx.x;
    int r = tid % NSUP, cg = tid / NSUP, base = 28 * cg;
    int bc0 = blockIdx.x * 4;
    int rmv[4];
    float A[4][28];
    __shared__ __align__(16) float srow[4][2][112];

#pragma unroll
    for (int m = 0; m < 4; m++) {
        int rm = r + 25 * m; if (rm >= NSUP) rm -= NSUP;
        rmv[m] = rm;
        int bc = bc0 + m, b = bc / NWAY, c = bc - b * NWAY;
        const float* K = g_krn + (size_t)b * NSUP * NSUP + rm * NSUP;
        float dval = 1.0f + g_d[b * NZV + c * NSUP + rm];
        float r1v  = g_r1[b * NZV + c * NSUP + rm];
        if (cg < 3) {
#pragma unroll
            for (int mm = 0; mm < 7; mm++) {
                float4 kv = *(const float4*)(K + base + 4 * mm);
                A[m][4*mm+0] = kv.x; A[m][4*mm+1] = kv.y;
                A[m][4*mm+2] = kv.z; A[m][4*mm+3] = kv.w;
            }
        } else {
#pragma unroll
            for (int mm = 0; mm < 4; mm++) {
                float4 kv = *(const float4*)(K + 84 + 4 * mm);
                A[m][4*mm+0] = kv.x; A[m][4*mm+1] = kv.y;
                A[m][4*mm+2] = kv.z; A[m][4*mm+3] = kv.w;
            }
            A[m][16] = r1v;
#pragma unroll
            for (int jj = 17; jj < 28; jj++) A[m][jj] = 0.f;
        }
#pragma unroll
        for (int jj = 0; jj < 28; jj++)
            if (base + jj == rm) A[m][jj] += dval;
        if (rm == 0) {
            float4* dst = (float4*)(srow[m][0] + base);
#pragma unroll
            for (int mm = 0; mm < 7; mm++)
                dst[mm] = make_float4(A[m][4*mm], A[m][4*mm+1], A[m][4*mm+2], A[m][4*mm+3]);
        }
    }
    __syncthreads();

    sweep4(A, srow, rmv, base);

#pragma unroll
    for (int m = 0; m < 4; m++) {
        int bc = bc0 + m, rm = rmv[m];
        float* Ho = g_Hinv + (size_t)bc * (NSUP * NSUP) + rm * NSUP;
        if (cg < 3) {
#pragma unroll
            for (int mm = 0; mm < 7; mm++)
                *(float4*)(Ho + base + 4 * mm) =
                    make_float4(A[m][4*mm], A[m][4*mm+1], A[m][4*mm+2], A[m][4*mm+3]);
        } else {
#pragma unroll
            for (int mm = 0; mm < 4; mm++)
                *(float4*)(Ho + 84 + 4 * mm) =
                    make_float4(A[m][4*mm], A[m][4*mm+1], A[m][4*mm+2], A[m][4*mm+3]);
            g_t[bc * NSUP + rm] = A[m][16];
        }
    }
}

// ---------------- Schur: 4 batches/block (grid=8, block=400) ----------------
__global__ void __launch_bounds__(400, 1) k_schur4(const int* __restrict__ lab) {
    int blk = blockIdx.x;
    int tid = threadIdx.x, lane = tid & 31, w = tid >> 5;
    int r = tid % NSUP, cg = tid / NSUP, base = 28 * cg;
    int rmv[4];
    float A[4][28];
    __shared__ __align__(16) float srow[4][2][112];
    __shared__ __align__(16) float s_dnu[4][NSUP];
    __shared__ __align__(16) float s_dz[4][NZV];
    __shared__ float s_red[400];
    __shared__ float s_alpha[4], s_mu[4];

    // Phase A: S_m = sum_c Hinv_c (row rmv[m]); border col = rhs
#pragma unroll
    for (int m = 0; m < 4; m++) {
        int rm = r + 25 * m; if (rm >= NSUP) rm -= NSUP;
        rmv[m] = rm;
        int bm = blk * 4 + m;
        const float* Hm = g_Hinv + (size_t)bm * NWAY * NSUP * NSUP + rm * NSUP;
        if (cg < 3) {
#pragma unroll
            for (int mm = 0; mm < 7; mm++) {
                float ax = 0.f, ay = 0.f, az = 0.f, aw = 0.f;
#pragma unroll
                for (int c = 0; c < NWAY; c++) {
                    float4 hv = *(const float4*)(Hm + (size_t)c * (NSUP * NSUP) + base + 4 * mm);
                    ax += hv.x; ay += hv.y; az += hv.z; aw += hv.w;
                }
                A[m][4*mm+0] = ax; A[m][4*mm+1] = ay;
                A[m][4*mm+2] = az; A[m][4*mm+3] = aw;
            }
        } else {
#pragma unroll
            for (int mm = 0; mm < 4; mm++) {
                float ax = 0.f, ay = 0.f, az = 0.f, aw = 0.f;
#pragma unroll
                for (int c = 0; c < NWAY; c++) {
                    float4 hv = *(const float4*)(Hm + (size_t)c * (NSUP * NSUP) + 84 + 4 * mm);
                    ax += hv.x; ay += hv.y; az += hv.z; aw += hv.w;
                }
                A[m][4*mm+0] = ax; A[m][4*mm+1] = ay;
                A[m][4*mm+2] = az; A[m][4*mm+3] = aw;
            }
            float v = g_rp2[bm * NSUP + rm];
#pragma unroll
            for (int c = 0; c < NWAY; c++) v += g_t[(bm * NWAY + c) * NSUP + rm];
            A[m][16] = v;
#pragma unroll
            for (int jj = 17; jj < 28; jj++) A[m][jj] = 0.f;
        }
        if (rm == 0) {
            float4* dst = (float4*)(srow[m][0] + base);
#pragma unroll
            for (int mm = 0; mm < 7; mm++)
                dst[mm] = make_float4(A[m][4*mm], A[m][4*mm+1], A[m][4*mm+2], A[m][4*mm+3]);
        }
    }
    __syncthreads();

    sweep4(A, srow, rmv, base);

    if (cg == 3) {
#pragma unroll
        for (int m = 0; m < 4; m++) s_dnu[m][rmv[m]] = A[m][16];
    }
    __syncthreads();

    // Phase D: dz rows (warps 0..11; vectorized, 25 active lanes, coalesced)
    if (w < 12) {
        for (int ri = w; ri < 4 * NZV; ri += 12) {
            int m = ri / NZV, rem = ri - m * NZV;
            int c = rem / NSUP, ss = rem - c * NSUP;
            int bm = blk * 4 + m;
            const float* Hrow = g_Hinv + (size_t)(bm * NWAY + c) * (NSUP * NSUP) + ss * NSUP;
            float acc = 0.f;
            if (lane < 25) {
                float4 hv = *(const float4*)(Hrow + 4 * lane);
                float4 dv = *(const float4*)(&s_dnu[m][4 * lane]);
                acc = hv.x * dv.x + hv.y * dv.y + hv.z * dv.z + hv.w * dv.w;
            }
#pragma unroll
            for (int off = 16; off; off >>= 1) acc += __shfl_xor_sync(0xffffffffu, acc, off);
            if (lane == 0)
                s_dz[m][rem] = g_t[(bm * NWAY + c) * NSUP + ss] - acc;
        }
    }
    __syncthreads();

    // Phase E: grp = cg (batch within block), gtid = r; element i = gtid + 100*q
    // => ss == gtid, c == q: dnu/nu/lab/rp2 all thread-local.
    int grp = cg, gtid = r;
    int bm = blk * 4 + grp;
    const float FINF = __int_as_float(0x7f800000);
    float dsv[10], dlv[10], sv[10], lv[10];
    float amin = FINF;
#pragma unroll
    for (int q = 0; q < 10; q++) {
        int i = gtid + NSUP * q;
        int gi = bm * NZV + i;
        float dz = s_dz[grp][i];
        float s0 = g_s[gi], l0 = g_lam[gi];
        float ds = -g_rp[gi] - dz;
        float dl = (-g_rc[gi] - l0 * ds) / s0;
        dsv[q] = ds; dlv[q] = dl; sv[q] = s0; lv[q] = l0;
        if (ds < 0.f) amin = fminf(amin, -s0 / ds);
        if (dl < 0.f) amin = fminf(amin, -l0 / dl);
    }
    s_red[tid] = amin;
    __syncthreads();
#pragma unroll
    for (int st = 64; st > 0; st >>= 1) {
        if (gtid < st && gtid + st < NSUP)
            s_red[grp * NSUP + gtid] = fminf(s_red[grp * NSUP + gtid],
                                             s_red[grp * NSUP + gtid + st]);
        __syncthreads();
    }
    if (gtid == 0) s_alpha[grp] = fminf(1.0f, 0.99f * s_red[grp * NSUP]);
    __syncthreads();
    float alpha = s_alpha[grp];

    float dnu_v = s_dnu[grp][gtid];
    float nn = g_nu[bm * NSUP + gtid] + alpha * dnu_v;
    g_nu[bm * NSUP + gtid] = nn;

    float gzn[10];
    float zsum = 0.f, muloc = 0.f;
#pragma unroll
    for (int q = 0; q < 10; q++) {
        int i = gtid + NSUP * q;
        int gi = bm * NZV + i;
        float dz = s_dz[grp][i];
        float zn = g_z[gi] + alpha * dz; g_z[gi] = zn; s_dz[grp][i] = zn; zsum += zn;
        float sn = sv[q] + alpha * dsv[q]; g_s[gi] = sn; sv[q] = sn;
        float ln = lv[q] + alpha * dlv[q]; g_lam[gi] = ln; lv[q] = ln;
        float gdz = g_r1[gi] - dnu_v - g_d[gi] * dz;   // (G dz)_i exactly
        float gz2 = g_gz[gi] + alpha * gdz; g_gz[gi] = gz2; gzn[q] = gz2;
        muloc += sn * ln;
    }
    g_rp2[bm * NSUP + gtid] = zsum;

    s_red[tid] = muloc;
    __syncthreads();
#pragma unroll
    for (int st = 64; st > 0; st >>= 1) {
        if (gtid < st && gtid + st < NSUP)
            s_red[grp * NSUP + gtid] += s_red[grp * NSUP + gtid + st];
        __syncthreads();
    }
    if (gtid == 0) s_mu[grp] = s_red[grp * NSUP] * (1.0f / (float)NZV);
    __syncthreads();
    float mu = s_mu[grp];
    int mylab = lab[bm * NSUP + gtid];

#pragma unroll
    for (int q = 0; q < 10; q++) {
        int i = gtid + NSUP * q;
        int gi = bm * NZV + i;
        float y = (mylab == q) ? 1.f : 0.f;
        float zn = s_dz[grp][i];
        float rd = gzn[q] - y + lv[q] + nn;
        float rp = zn + sv[q] - 0.1f * y;
        float rc = lv[q] * sv[q] - 0.1f * mu;
        float invs = 1.0f / sv[q];
        g_rp[gi] = rp;
        g_rc[gi] = rc;
        g_d [gi] = lv[q] * invs;
        g_r1[gi] = -rd + (rc - lv[q] * rp) * invs;
    }
}

// ---------------- logits epilogue ----------------
__global__ void __launch_bounds__(256) k_logits(float* __restrict__ out) {
    int b = blockIdx.x, tid = threadIdx.x;
    __shared__ float sh_z[NZV];
    for (int i = tid; i < NZV; i += 256) sh_z[i] = g_z[b * NZV + i];
    __syncthreads();
    const float* cb = &g_compat[b * NSUP * NQRY];
    for (int o = tid; o < NQRY * NWAY; o += 256) {
        int q = o / NWAY, n = o - q * NWAY;
        float acc = 0.f;
        for (int s = 0; s < NSUP; s++)
            acc = fmaf(cb[s * NQRY + q], sh_z[n * NSUP + s], acc);
        out[b * NQRY * NWAY + o] = acc;
    }
}

// ---------------- launcher ----------------
extern "C" void kernel_launch(void* const* d_in, const int* in_sizes, int n_in,
                              void* d_out, int out_size) {
    const float* sup = (const float*)d_in[0];
    const int*   lab = (const int*)  d_in[1];
    const float* qry = (const float*)d_in[2];
    float* out = (float*)d_out;

    k_gram<<<dim3(NBATCH, 4), 400>>>(sup, qry);
    k_init<<<NBATCH, 256>>>(lab);
    for (int it = 0; it < 15; ++it) {
        k_invert4<<<NBATCH * NWAY / 4, 400>>>();
        k_schur4<<<NBATCH / 4, 400>>>(lab);
    }
    k_logits<<<NBATCH, 256>>>(out);
}

// round 11
// speedup vs baseline: 3.2196x; 3.2196x over previous
#include <cuda_runtime.h>
#include <cuda_bf16.h>

#define NBATCH 32
#define NSUP   100
#define NWAY   10
#define NZV    1000
#define NQRY   150

// ---------------- device scratch ----------------
__device__ float g_krn   [NBATCH * NSUP * NSUP];          // sup sup^T (bitwise symmetric)
__device__ float g_compat[NBATCH * NSUP * NQRY];
__device__ float g_Hinv  [NBATCH * NWAY * NSUP * NSUP];   // [bc][j*100+i] (symmetric)
__device__ float g_t     [NBATCH * NWAY * NSUP];
// all NZV-state arrays use i2 = c*100 + ss layout
__device__ float g_z  [NBATCH * NZV];
__device__ float g_s  [NBATCH * NZV];
__device__ float g_lam[NBATCH * NZV];
__device__ float g_gz [NBATCH * NZV];
__device__ float g_rp [NBATCH * NZV];
__device__ float g_rc [NBATCH * NZV];
__device__ float g_r1 [NBATCH * NZV];
__device__ float g_d  [NBATCH * NZV];
__device__ float g_nu [NBATCH * NSUP];
__device__ float g_rp2[NBATCH * NSUP];

// ---------------- gram: kernel (100x100) + compat (100x150) ----------------
__global__ void __launch_bounds__(400) k_gram(const float* __restrict__ sup,
                                              const float* __restrict__ qry) {
    int b  = blockIdx.x;
    int c0 = blockIdx.y * 64;
    __shared__ __align__(16) float As[32 * 100];
    __shared__ __align__(16) float Bs[32 * 64];
    int tid = threadIdx.x;
    int tx = tid & 15;
    int ty = tid >> 4;
    float acc[4][4];
#pragma unroll
    for (int u = 0; u < 4; u++)
#pragma unroll
        for (int v = 0; v < 4; v++) acc[u][v] = 0.f;

    const float* supb = sup + (size_t)b * NSUP * 512;
    const float* qryb = qry + (size_t)b * NQRY * 512;

    for (int kt = 0; kt < 512; kt += 32) {
        __syncthreads();
        for (int e = tid; e < NSUP * 32; e += 400) {
            int r = e >> 5, kk = e & 31;
            As[kk * 100 + r] = supb[r * 512 + kt + kk];
        }
        for (int e = tid; e < 64 * 32; e += 400) {
            int cc = e >> 5, kk = e & 31;
            int col = c0 + cc;
            float v = 0.f;
            if (col < NSUP)      v = supb[col * 512 + kt + kk];
            else if (col < 250)  v = qryb[(col - NSUP) * 512 + kt + kk];
            Bs[kk * 64 + cc] = v;
        }
        __syncthreads();
#pragma unroll
        for (int kk = 0; kk < 32; kk++) {
            float4 a  = *(const float4*)(As + kk * 100 + 4 * ty);
            float4 bb = *(const float4*)(Bs + kk * 64 + 4 * tx);
            acc[0][0] = fmaf(a.x, bb.x, acc[0][0]); acc[0][1] = fmaf(a.x, bb.y, acc[0][1]);
            acc[0][2] = fmaf(a.x, bb.z, acc[0][2]); acc[0][3] = fmaf(a.x, bb.w, acc[0][3]);
            acc[1][0] = fmaf(a.y, bb.x, acc[1][0]); acc[1][1] = fmaf(a.y, bb.y, acc[1][1]);
            acc[1][2] = fmaf(a.y, bb.z, acc[1][2]); acc[1][3] = fmaf(a.y, bb.w, acc[1][3]);
            acc[2][0] = fmaf(a.z, bb.x, acc[2][0]); acc[2][1] = fmaf(a.z, bb.y, acc[2][1]);
            acc[2][2] = fmaf(a.z, bb.z, acc[2][2]); acc[2][3] = fmaf(a.z, bb.w, acc[2][3]);
            acc[3][0] = fmaf(a.w, bb.x, acc[3][0]); acc[3][1] = fmaf(a.w, bb.y, acc[3][1]);
            acc[3][2] = fmaf(a.w, bb.z, acc[3][2]); acc[3][3] = fmaf(a.w, bb.w, acc[3][3]);
        }
    }
#pragma unroll
    for (int u = 0; u < 4; u++) {
        int r = 4 * ty + u;
#pragma unroll
        for (int v = 0; v < 4; v++) {
            int col = c0 + 4 * tx + v;
            if (col < NSUP)
                g_krn[b * NSUP * NSUP + r * NSUP + col] = acc[u][v];
            else if (col < 250)
                g_compat[b * NSUP * NQRY + r * NQRY + (col - NSUP)] = acc[u][v];
        }
    }
}

// ---------------- init (i2 layout) ----------------
__global__ void __launch_bounds__(256) k_init(const int* __restrict__ lab) {
    int b = blockIdx.x, tid = threadIdx.x;
    for (int i = tid; i < NZV; i += 256) {
        int gi = b * NZV + i;
        int ss = i % NSUP, c = i / NSUP;
        float y = (lab[b * NSUP + ss] == c) ? 1.f : 0.f;
        g_z[gi] = 0.f; g_s[gi] = 1.f; g_lam[gi] = 1.f; g_gz[gi] = 0.f;
        float rd = 1.f - y;
        float rp = 1.f - 0.1f * y;
        float rc = 0.9f;
        g_rp[gi] = rp;
        g_rc[gi] = rc;
        g_d [gi] = 1.f;
        g_r1[gi] = -rd + (rc - rp);
    }
    for (int ss = tid; ss < NSUP; ss += 256) {
        g_nu [b * NSUP + ss] = 0.f;
        g_rp2[b * NSUP + ss] = 0.f;
    }
}

// ---------------- rank-2 symmetric sweep (register-resident) ----------------
// Thread owns row r, cols [base, base+28) of the 112-wide augmented row
// (col 100 = rhs border). Eliminates pivots k and k+1 per barrier interval.
// srow[buf][0] = pivot row k, srow[buf][1] = pivot row k+1 (both swept thru k-1).
__device__ __forceinline__ void sweep_r2(float A[28], float srow[2][2][112],
                                         int r, int base, bool active) {
    for (int k = 0; k < NSUP; k += 2) {
        int buf = (k >> 1) & 1, nb = buf ^ 1;
        if (active) {
            const float* rA = srow[buf][0];
            const float* rB = srow[buf][1];
            float invp1 = __fdividef(1.0f, rA[k]);
            float sk1   = rA[k + 1];
            float t1k1  = sk1 * invp1;                       // mult of row k+1 wrt pivot k
            float p2kk  = fmaf(-t1k1, sk1, rB[k + 1]);       // pivot for step k+1
            float invp2 = __fdividef(1.0f, p2kk);
            float srA = rA[r], srB = rB[r];
            float t1  = (r < k) ? -srA * invp1 : srA * invp1;
            float p2r = (r == k) ? -t1k1 : fmaf(-t1k1, srA, srB);
            float t2  = (r < k + 1) ? -p2r * invp2 : p2r * invp2;
            const float4* rAv = (const float4*)(rA + base);
            const float4* rBv = (const float4*)(rB + base);

            if (r == k) {
                // own row = rA: scale by invp1, then update by pivot k+1
#pragma unroll
                for (int m = 0; m < 7; m++) {
                    float4 qb = rBv[m];
#pragma unroll
                    for (int cmp = 0; cmp < 4; cmp++) {
                        int j = base + 4 * m + cmp;
                        float qa = A[4 * m + cmp];
                        float u  = (j == k) ? invp1 : qa * invp1;
                        float p2 = (j == k) ? -t1k1
                                 : fmaf(-t1k1, qa, ((const float*)&qb)[cmp]);
                        float v  = fmaf(-t2, p2, u);
                        A[4 * m + cmp] = (j == k + 1) ? -t2 : v;
                    }
                }
            } else if (r == k + 1) {
                // own row = rB: update by pivot k, then scale by invp2
#pragma unroll
                for (int m = 0; m < 7; m++) {
                    float4 qa = rAv[m];
#pragma unroll
                    for (int cmp = 0; cmp < 4; cmp++) {
                        int j = base + 4 * m + cmp;
                        float p2 = (j == k) ? -t1k1
                                 : fmaf(-t1k1, ((const float*)&qa)[cmp], A[4 * m + cmp]);
                        A[4 * m + cmp] = (j == k + 1) ? invp2 : p2 * invp2;
                    }
                }
            } else if (k >= base - 1 && k < base + 28) {
                // fixup chunk (k or k+1 lands in this thread's columns)
#pragma unroll
                for (int m = 0; m < 7; m++) {
                    float4 qa = rAv[m];
                    float4 qb = rBv[m];
#pragma unroll
                    for (int cmp = 0; cmp < 4; cmp++) {
                        int j = base + 4 * m + cmp;
                        float qaj = ((const float*)&qa)[cmp];
                        float u  = fmaf(-t1, qaj, A[4 * m + cmp]);
                        u = (j == k) ? -t1 : u;
                        float p2 = fmaf(-t1k1, qaj, ((const float*)&qb)[cmp]);
                        p2 = (j == k) ? -t1k1 : p2;
                        float v  = fmaf(-t2, p2, u);
                        A[4 * m + cmp] = (j == k + 1) ? -t2 : v;
                    }
                }
            } else {
                // clean chunk: pure rank-2 update
#pragma unroll
                for (int m = 0; m < 7; m++) {
                    float4 qa = rAv[m];
                    float4 qb = rBv[m];
#pragma unroll
                    for (int cmp = 0; cmp < 4; cmp++) {
                        float qaj = ((const float*)&qa)[cmp];
                        float u  = fmaf(-t1, qaj, A[4 * m + cmp]);
                        float p2 = fmaf(-t1k1, qaj, ((const float*)&qb)[cmp]);
                        A[4 * m + cmp] = fmaf(-t2, p2, u);
                    }
                }
            }

            // stage next pivot pair
            if (k + 2 < NSUP) {
                if (r == k + 2) {
                    float4* dst = (float4*)(srow[nb][0] + base);
#pragma unroll
                    for (int m = 0; m < 7; m++)
                        dst[m] = make_float4(A[4*m], A[4*m+1], A[4*m+2], A[4*m+3]);
                }
                if (r == k + 3) {
                    float4* dst = (float4*)(srow[nb][1] + base);
#pragma unroll
                    for (int m = 0; m < 7; m++)
                        dst[m] = make_float4(A[4*m], A[4*m+1], A[4*m+2], A[4*m+3]);
                }
            }
        }
        __syncthreads();
    }
}

// ---------------- per-class inversion (grid=320, block=400) ----------------
__global__ void __launch_bounds__(400, 2) k_invert() {
    int bc = blockIdx.x;
    int b = bc / NWAY, c = bc - b * NWAY;
    int tid = threadIdx.x;
    int r = tid % NSUP, cg = tid / NSUP;
    int base = 28 * cg;
    float A[28];
    __shared__ __align__(16) float srow[2][2][112];

    const float* K = g_krn + (size_t)b * NSUP * NSUP;
    float dval = 1.0f + g_d[b * NZV + c * NSUP + r];
    float r1v  = g_r1[b * NZV + c * NSUP + r];
#pragma unroll
    for (int jj = 0; jj < 28; jj++) {
        int j = base + jj;
        float v = 0.f;
        if (j < NSUP) { v = K[j * NSUP + r]; if (j == r) v += dval; }   // K symmetric
        else if (j == NSUP) v = r1v;
        A[jj] = v;
    }
    if (r <= 1) {
        float4* dst = (float4*)(srow[0][r] + base);
#pragma unroll
        for (int m = 0; m < 7; m++)
            dst[m] = make_float4(A[4*m], A[4*m+1], A[4*m+2], A[4*m+3]);
    }
    __syncthreads();

    sweep_r2(A, srow, r, base, true);

    // coalesced transposed store (Hinv symmetric -> identical data)
    float* Ho = g_Hinv + (size_t)bc * (NSUP * NSUP);
#pragma unroll
    for (int jj = 0; jj < 28; jj++) {
        int j = base + jj;
        if (j < NSUP) Ho[j * NSUP + r] = A[jj];
    }
    if (cg == 3) g_t[bc * NSUP + r] = A[16];   // col 100 -> t = Hinv r1
}

// ---------------- Schur solve + step + residuals (grid=32, block=512) ----------------
__global__ void __launch_bounds__(512) k_schur(const int* __restrict__ lab) {
    int b = blockIdx.x, tid = threadIdx.x;
    int lane = tid & 31, w = tid >> 5;
    int r = tid % NSUP, cg = tid / NSUP;   // meaningful for tid<400
    int base = 28 * cg;
    float A[28];
    __shared__ __align__(16) float srow[2][2][112];
    __shared__ float s_dnu[NSUP];
    __shared__ float s_dz[NZV];
    __shared__ float red[16];
    __shared__ float s_res[2];

    const float* Hb = g_Hinv + (size_t)b * NWAY * NSUP * NSUP;

    if (tid < 400) {
        // S = sum_c Hinv_c (rows via symmetric/coalesced reads); border col = rhs
#pragma unroll
        for (int jj = 0; jj < 28; jj++) {
            int j = base + jj;
            float v = 0.f;
            if (j < NSUP) {
#pragma unroll
                for (int c = 0; c < NWAY; c++)
                    v += Hb[(size_t)c * (NSUP * NSUP) + j * NSUP + r];
            } else if (j == NSUP) {
                v = g_rp2[b * NSUP + r];
#pragma unroll
                for (int c = 0; c < NWAY; c++)
                    v += g_t[(b * NWAY + c) * NSUP + r];
            }
            A[jj] = v;
        }
        if (r <= 1) {
            float4* dst = (float4*)(srow[0][r] + base);
#pragma unroll
            for (int m = 0; m < 7; m++)
                dst[m] = make_float4(A[4*m], A[4*m+1], A[4*m+2], A[4*m+3]);
        }
    }
    __syncthreads();

    sweep_r2(A, srow, r, base, tid < 400);

    if (tid < 400 && cg == 3) s_dnu[r] = A[16];   // dnu
    __syncthreads();

    // Phase D: dz (warp per i2 row, coalesced over j thanks to symmetric storage)
    for (int ri = w; ri < NZV; ri += 16) {
        int c = ri / NSUP, ss = ri - c * NSUP;
        const float* Hrow = Hb + (size_t)c * (NSUP * NSUP) + ss * NSUP;
        float acc = 0.f;
#pragma unroll
        for (int m = 0; m < 4; m++) {
            int j = lane + 32 * m;
            if (j < NSUP) acc = fmaf(Hrow[j], s_dnu[j], acc);
        }
#pragma unroll
        for (int off = 16; off; off >>= 1) acc += __shfl_xor_sync(0xffffffffu, acc, off);
        if (lane == 0) s_dz[ri] = g_t[(b * NWAY + c) * NSUP + ss] - acc;
    }
    __syncthreads();

    // Phase E: steps, alpha, state update, residuals (i2 layout)
    const float FINF = __int_as_float(0x7f800000);
    float dzv[2], dsv[2], dlv[2], sv[2], lv[2], zv[2], gzv[2];
    float amin = FINF;
#pragma unroll
    for (int q = 0; q < 2; q++) {
        int i = tid + q * 512;
        if (i < NZV) {
            int gi = b * NZV + i;
            float dz = s_dz[i];
            float s0 = g_s[gi], l0 = g_lam[gi];
            float ds = -g_rp[gi] - dz;
            float dl = (-g_rc[gi] - l0 * ds) / s0;
            dzv[q] = dz; dsv[q] = ds; dlv[q] = dl; sv[q] = s0; lv[q] = l0;
            if (ds < 0.f) amin = fminf(amin, -s0 / ds);
            if (dl < 0.f) amin = fminf(amin, -l0 / dl);
        }
    }
#pragma unroll
    for (int off = 16; off; off >>= 1) amin = fminf(amin, __shfl_xor_sync(0xffffffffu, amin, off));
    if (lane == 0) red[w] = amin;
    __syncthreads();
    if (w == 0) {
        float v = (lane < 16) ? red[lane] : FINF;
#pragma unroll
        for (int off = 8; off; off >>= 1) v = fminf(v, __shfl_xor_sync(0xffffffffu, v, off));
        if (lane == 0) s_res[0] = fminf(1.0f, 0.99f * v);
    }
    __syncthreads();
    float alpha = s_res[0];

    float muloc = 0.f;
#pragma unroll
    for (int q = 0; q < 2; q++) {
        int i = tid + q * 512;
        if (i < NZV) {
            int gi = b * NZV + i;
            int ss = i % NSUP;
            float zn = g_z[gi] + alpha * dzv[q]; g_z[gi] = zn; zv[q] = zn;
            float sn = sv[q] + alpha * dsv[q];   g_s[gi] = sn; sv[q] = sn;
            float ln = lv[q] + alpha * dlv[q];   g_lam[gi] = ln; lv[q] = ln;
            float gdz = g_r1[gi] - s_dnu[ss] - g_d[gi] * dzv[q];   // (G dz)_i exactly
            float gzn = g_gz[gi] + alpha * gdz;  g_gz[gi] = gzn; gzv[q] = gzn;
            muloc += sn * ln;
            s_dz[i] = zn;   // reuse as z_new
        }
    }
#pragma unroll
    for (int off = 16; off; off >>= 1) muloc += __shfl_xor_sync(0xffffffffu, muloc, off);
    if (lane == 0) red[w] = muloc;
    __syncthreads();
    if (w == 0) {
        float v = (lane < 16) ? red[lane] : 0.f;
#pragma unroll
        for (int off = 8; off; off >>= 1) v += __shfl_xor_sync(0xffffffffu, v, off);
        if (lane == 0) s_res[1] = v;
    }
    __syncthreads();
    float mu = s_res[1] * (1.0f / (float)NZV);

    // nu update (overwrite s_dnu with nu_new) + rp2
    if (tid < NSUP) {
        float nn = g_nu[b * NSUP + tid] + alpha * s_dnu[tid];
        s_dnu[tid] = nn;
        g_nu[b * NSUP + tid] = nn;
        float acc = 0.f;
#pragma unroll
        for (int c = 0; c < NWAY; c++) acc += s_dz[c * NSUP + tid];
        g_rp2[b * NSUP + tid] = acc;
    }
    __syncthreads();

    // next-iteration residuals (elementwise; no matvec)
#pragma unroll
    for (int q = 0; q < 2; q++) {
        int i = tid + q * 512;
        if (i < NZV) {
            int gi = b * NZV + i;
            int ss = i % NSUP, c = i / NSUP;
            float y = (lab[b * NSUP + ss] == c) ? 1.f : 0.f;
            float rd = gzv[q] - y + lv[q] + s_dnu[ss];
            float rp = zv[q] + sv[q] - 0.1f * y;
            float rc = lv[q] * sv[q] - 0.1f * mu;
            float invs = 1.0f / sv[q];
            g_rp[gi] = rp;
            g_rc[gi] = rc;
            g_d [gi] = lv[q] * invs;
            g_r1[gi] = -rd + (rc - lv[q] * rp) * invs;
        }
    }
}

// ---------------- logits epilogue ----------------
__global__ void __launch_bounds__(256) k_logits(float* __restrict__ out) {
    int b = blockIdx.x, tid = threadIdx.x;
    __shared__ float sh_z[NZV];
    for (int i = tid; i < NZV; i += 256) sh_z[i] = g_z[b * NZV + i];
    __syncthreads();
    const float* cb = &g_compat[b * NSUP * NQRY];
    for (int o = tid; o < NQRY * NWAY; o += 256) {
        int q = o / NWAY, n = o - q * NWAY;
        float acc = 0.f;
        for (int s = 0; s < NSUP; s++)
            acc = fmaf(cb[s * NQRY + q], sh_z[n * NSUP + s], acc);
        out[b * NQRY * NWAY + o] = acc;
    }
}

// ---------------- launcher ----------------
extern "C" void kernel_launch(void* const* d_in, const int* in_sizes, int n_in,
                              void* d_out, int out_size) {
    const float* sup = (const float*)d_in[0];
    const int*   lab = (const int*)  d_in[1];
    const float* qry = (const float*)d_in[2];
    float* out = (float*)d_out;

    k_gram<<<dim3(NBATCH, 4), 400>>>(sup, qry);
    k_init<<<NBATCH, 256>>>(lab);
    for (int it = 0; it < 15; ++it) {
        k_invert<<<NBATCH * NWAY, 400>>>();
        k_schur<<<NBATCH, 512>>>(lab);
    }
    k_logits<<<NBATCH, 256>>>(out);
}